// round 3
// baseline (speedup 1.0000x reference)
#include <cuda_runtime.h>
#include <cuda_bf16.h>

#define NN 100000
#define NE 1600000
#define IND 128
#define HID 32
#define OUTD 64
#define NREL 8
#define NCOL 288   // 8*32 + 32 (root)

// -------- scratch (static device memory; 16B-aligned for float4/REDG.v4) --------
__device__ __align__(16) float g_wcat[IND * NCOL];      // packed [k][j]: j<256 -> W1[r][k][h], else root1
__device__ __align__(16) float g_y1[(size_t)NN * NCOL]; // x @ [W1 | root1]  (115 MB)
__device__ __align__(16) float g_agg1[NN * HID];        // layer-1 aggregation
__device__ __align__(16) float g_deg[NN];
__device__ __align__(16) float g_h[NN * HID];           // layer-1 output (post-relu)
__device__ __align__(16) float g_A2[(size_t)NN * 256];  // layer-2 relation-factored accum (102 MB)
__device__ __align__(16) float g_W2p[512];              // [r*32+k][c]  = W2 @ lin_w
__device__ __align__(16) float g_r2p[64];               // [k][c]       = root2 @ lin_w
__device__ __align__(16) float g_bp[2];                 // b2 @ lin_w + lin_b
__device__ int g_is64;                                  // edge arrays are int64 (vs int32)

// -------- dtype detection: int64 layout has zero high words for indices < 2^31 --------
__global__ void detect_kernel(const int* __restrict__ ei_raw) {
    if (threadIdx.x == 0 && blockIdx.x == 0) {
        int is64 = 1;
        for (int i = 0; i < 1024; i++)
            if (ei_raw[2 * i + 1] != 0) { is64 = 0; break; }
        g_is64 = is64;
    }
}

__device__ __forceinline__ int edge_at(const void* __restrict__ p, size_t i) {
    if (g_is64) return (int)((const long long*)p)[i];
    return ((const int*)p)[i];
}

// -------- prep: pack weights, fold classifier --------
__global__ void prep_kernel(const float* __restrict__ W1, const float* __restrict__ root1,
                            const float* __restrict__ W2, const float* __restrict__ root2,
                            const float* __restrict__ b2, const float* __restrict__ lin_w,
                            const float* __restrict__ lin_b) {
    int t = blockIdx.x * blockDim.x + threadIdx.x;
    int stride = gridDim.x * blockDim.x;
    // pack Wcat [128][288]
    for (int i = t; i < IND * NCOL; i += stride) {
        int k = i / NCOL, j = i % NCOL;
        float v;
        if (j < 256) v = W1[(j >> 5) * (IND * HID) + k * HID + (j & 31)];
        else         v = root1[k * HID + (j - 256)];
        g_wcat[i] = v;
    }
    // W2p: idx = r*32+k, W2 is [8][32][64]
    if (t < 512) {
        int idx = t >> 1, c = t & 1;
        const float* wrow = W2 + idx * OUTD;
        float s = 0.f;
        for (int o = 0; o < OUTD; o++) s += wrow[o] * lin_w[o * 2 + c];
        g_W2p[t] = s;
    }
    if (t < 64) {
        int k = t >> 1, c = t & 1;
        float s = 0.f;
        for (int o = 0; o < OUTD; o++) s += root2[k * OUTD + o] * lin_w[o * 2 + c];
        g_r2p[t] = s;
    }
    if (t < 2) {
        float s = lin_b[t];
        for (int o = 0; o < OUTD; o++) s += b2[o] * lin_w[o * 2 + t];
        g_bp[t] = s;
    }
}

// -------- zero accumulators --------
__global__ void zero_kernel() {
    int t = blockIdx.x * blockDim.x + threadIdx.x;
    int stride = gridDim.x * blockDim.x;
    float4 z = make_float4(0.f, 0.f, 0.f, 0.f);
    for (int i = t; i < NN * (HID / 4); i += stride) ((float4*)g_agg1)[i] = z;
    for (int i = t; i < NN * 64; i += stride)        ((float4*)g_A2)[i]   = z;
    for (int i = t; i < NN / 4; i += stride)         ((float4*)g_deg)[i]  = z;
}

// -------- GEMM: y1[N,288] = x[N,128] @ wcat[128,288] --------
#define BM 128
#define BN 96
#define BK 16
#define TM 8
#define TN 6
__global__ __launch_bounds__(256) void gemm_kernel(const float* __restrict__ x) {
    __shared__ float As[BK][BM + 4];
    __shared__ float Bs[BK][BN];
    int block_row = blockIdx.x * BM;
    int block_col = blockIdx.y * BN;
    int tid = threadIdx.x;
    int tx = tid & 15, ty = tid >> 4;
    float acc[TM][TN];
#pragma unroll
    for (int i = 0; i < TM; i++)
#pragma unroll
        for (int j = 0; j < TN; j++) acc[i][j] = 0.f;

    for (int k0 = 0; k0 < IND; k0 += BK) {
        // load A tile 128x16 (transposed into smem)
#pragma unroll
        for (int i = tid; i < BM * BK; i += 256) {
            int r = i / BK, kk = i % BK;
            int gr = block_row + r;
            As[kk][r] = (gr < NN) ? x[(size_t)gr * IND + k0 + kk] : 0.f;
        }
        // load B tile 16x96
#pragma unroll
        for (int i = tid; i < BK * BN; i += 256) {
            int kk = i / BN, j = i % BN;
            Bs[kk][j] = g_wcat[(k0 + kk) * NCOL + block_col + j];
        }
        __syncthreads();
#pragma unroll
        for (int kk = 0; kk < BK; kk++) {
            float a[TM], b[TN];
#pragma unroll
            for (int i = 0; i < TM; i++) a[i] = As[kk][ty * TM + i];
#pragma unroll
            for (int j = 0; j < TN; j++) b[j] = Bs[kk][tx * TN + j];
#pragma unroll
            for (int i = 0; i < TM; i++)
#pragma unroll
                for (int j = 0; j < TN; j++) acc[i][j] += a[i] * b[j];
        }
        __syncthreads();
    }
#pragma unroll
    for (int i = 0; i < TM; i++) {
        int gr = block_row + ty * TM + i;
        if (gr < NN) {
#pragma unroll
            for (int j = 0; j < TN; j++)
                g_y1[(size_t)gr * NCOL + block_col + tx * TN + j] = acc[i][j];
        }
    }
}

// -------- layer-1 scatter: agg1[dst] += y1[src, rel] (32 floats) + degree --------
__global__ __launch_bounds__(256) void scatter1_kernel(const void* __restrict__ ei,
                                                       const void* __restrict__ et) {
    int t = blockIdx.x * blockDim.x + threadIdx.x;   // NE*8 threads exactly
    int e = t >> 3, c = t & 7;
    int src = edge_at(ei, e);
    int dst = edge_at(ei, (size_t)NE + e);
    int r   = edge_at(et, e);
    float4 v = *(const float4*)&g_y1[(size_t)src * NCOL + r * HID + c * 4];
    atomicAdd((float4*)&g_agg1[dst * HID + c * 4], v);
    if (c == 0) atomicAdd(&g_deg[dst], 1.0f);
}

// -------- h = relu(agg1/deg + x@root1 + b1) --------
__global__ __launch_bounds__(256) void h_kernel(const float* __restrict__ b1) {
    int i = blockIdx.x * blockDim.x + threadIdx.x;   // NN*32 threads exactly
    int n = i >> 5, j = i & 31;
    float d = g_deg[n];
    d = d > 1.f ? d : 1.f;
    float v = g_agg1[i] / d + g_y1[(size_t)n * NCOL + 256 + j] + b1[j];
    g_h[i] = v > 0.f ? v : 0.f;
}

// -------- layer-2 scatter (relation-factored): A2[dst][rel] += h[src] --------
__global__ __launch_bounds__(256) void scatter2_kernel(const void* __restrict__ ei,
                                                       const void* __restrict__ et) {
    int t = blockIdx.x * blockDim.x + threadIdx.x;   // NE*8 threads exactly
    int e = t >> 3, c = t & 7;
    int src = edge_at(ei, e);
    int dst = edge_at(ei, (size_t)NE + e);
    int r   = edge_at(et, e);
    float4 v = *(const float4*)&g_h[src * HID + c * 4];
    atomicAdd((float4*)&g_A2[(size_t)dst * 256 + r * HID + c * 4], v);
}

// -------- output: out[n] = (A2[n]/deg) . W2p + h[n] . r2p + bp ; one warp per node --------
__global__ __launch_bounds__(256) void out_kernel(float* __restrict__ out) {
    int tid = threadIdx.x;
    int lane = tid & 31, warp = tid >> 5;
    int n = blockIdx.x * 8 + warp;
    // per-lane fixed weights: k = u*128 + lane*4 + m
    float wk[2][4][2];
#pragma unroll
    for (int u = 0; u < 2; u++)
#pragma unroll
        for (int m = 0; m < 4; m++) {
            int k = u * 128 + lane * 4 + m;
            wk[u][m][0] = g_W2p[k * 2 + 0];
            wk[u][m][1] = g_W2p[k * 2 + 1];
        }
    float r20 = g_r2p[lane * 2 + 0];
    float r21 = g_r2p[lane * 2 + 1];

    if (n >= NN) return;
    const float4* a = (const float4*)&g_A2[(size_t)n * 256];
    float c0 = 0.f, c1 = 0.f;
#pragma unroll
    for (int u = 0; u < 2; u++) {
        float4 v = a[u * 32 + lane];  // coalesced
        c0 += v.x * wk[u][0][0] + v.y * wk[u][1][0] + v.z * wk[u][2][0] + v.w * wk[u][3][0];
        c1 += v.x * wk[u][0][1] + v.y * wk[u][1][1] + v.z * wk[u][2][1] + v.w * wk[u][3][1];
    }
    float d = g_deg[n];
    d = d > 1.f ? d : 1.f;
    float inv = 1.f / d;
    float hv = g_h[n * HID + lane];
    float v0 = c0 * inv + hv * r20;
    float v1 = c1 * inv + hv * r21;
#pragma unroll
    for (int off = 16; off; off >>= 1) {
        v0 += __shfl_xor_sync(0xFFFFFFFFu, v0, off);
        v1 += __shfl_xor_sync(0xFFFFFFFFu, v1, off);
    }
    if (lane == 0) {
        out[n * 2 + 0] = v0 + g_bp[0];
        out[n * 2 + 1] = v1 + g_bp[1];
    }
}

extern "C" void kernel_launch(void* const* d_in, const int* in_sizes, int n_in,
                              void* d_out, int out_size) {
    const float* x        = (const float*)d_in[0];
    const void*  ei       = d_in[1];
    const void*  et       = d_in[2];
    const float* W1       = (const float*)d_in[3];
    const float* root1    = (const float*)d_in[4];
    const float* b1       = (const float*)d_in[5];
    const float* W2       = (const float*)d_in[6];
    const float* root2    = (const float*)d_in[7];
    const float* b2       = (const float*)d_in[8];
    const float* lin_w    = (const float*)d_in[9];
    const float* lin_b    = (const float*)d_in[10];
    float* out            = (float*)d_out;

    detect_kernel<<<1, 32>>>((const int*)ei);
    prep_kernel<<<145, 256>>>(W1, root1, W2, root2, b2, lin_w, lin_b);
    zero_kernel<<<8192, 256>>>();
    gemm_kernel<<<dim3((NN + BM - 1) / BM, NCOL / BN), 256>>>(x);
    scatter1_kernel<<<(NE * 8) / 256, 256>>>(ei, et);
    h_kernel<<<(NN * HID) / 256, 256>>>(b1);
    scatter2_kernel<<<(NE * 8) / 256, 256>>>(ei, et);
    out_kernel<<<(NN + 7) / 8, 256>>>(out);
}

// round 4
// speedup vs baseline: 1.6693x; 1.6693x over previous
#include <cuda_runtime.h>
#include <cuda_bf16.h>
#include <cstdint>

#define NN 100000
#define NE 1600000
#define IND 128
#define HID 32
#define OUTD 64
#define NREL 8
#define NCOL 288   // 8*32 + 32 (root)

// -------- scratch (static device memory; 16B-aligned) --------
__device__ __align__(16) float g_wcat[IND * NCOL];      // packed [k][j]: j<256 -> W1[r][k][h], else root1
__device__ __align__(16) float g_y1[(size_t)NN * NCOL]; // x @ [W1 | root1]  (115 MB)
__device__ __align__(16) float g_agg1[NN * HID];        // layer-1 aggregation
__device__ __align__(16) float g_deg[NN];
__device__ __align__(16) float g_h[NN * HID];           // layer-1 output (post-relu)
__device__ __align__(16) float g_y2[NN * 16];           // [n][r][c]: h @ W2p  (6.4 MB)
__device__ __align__(16) float g_acc2[NN * 2];          // layer-2 folded accumulator
__device__ __align__(16) float g_W2p[512];              // [(r*32+k)*2+c] = W2 @ lin_w
__device__ __align__(16) float g_r2p[64];               // [k*2+c]        = root2 @ lin_w
__device__ __align__(16) float g_bp[2];                 // b2 @ lin_w + lin_b
__device__ int g_is64;                                  // edge arrays are int64 (vs int32)

// -------- dtype detection: int64 layout has zero high words for indices < 2^31 --------
__global__ void detect_kernel(const int* __restrict__ ei_raw) {
    if (threadIdx.x == 0 && blockIdx.x == 0) {
        int is64 = 1;
        for (int i = 0; i < 1024; i++)
            if (ei_raw[2 * i + 1] != 0) { is64 = 0; break; }
        g_is64 = is64;
    }
}

__device__ __forceinline__ int edge_at(const void* __restrict__ p, size_t i) {
    if (g_is64) return (int)((const long long*)p)[i];
    return ((const int*)p)[i];
}

// -------- prep: pack weights, fold classifier --------
__global__ void prep_kernel(const float* __restrict__ W1, const float* __restrict__ root1,
                            const float* __restrict__ W2, const float* __restrict__ root2,
                            const float* __restrict__ b2, const float* __restrict__ lin_w,
                            const float* __restrict__ lin_b) {
    int t = blockIdx.x * blockDim.x + threadIdx.x;
    int stride = gridDim.x * blockDim.x;
    for (int i = t; i < IND * NCOL; i += stride) {
        int k = i / NCOL, j = i % NCOL;
        float v;
        if (j < 256) v = W1[(j >> 5) * (IND * HID) + k * HID + (j & 31)];
        else         v = root1[k * HID + (j - 256)];
        g_wcat[i] = v;
    }
    if (t < 512) {                       // idx = r*32+k over [0,256), c in {0,1}
        int idx = t >> 1, c = t & 1;
        const float* wrow = W2 + idx * OUTD;
        float s = 0.f;
        for (int o = 0; o < OUTD; o++) s += wrow[o] * lin_w[o * 2 + c];
        g_W2p[t] = s;
    }
    if (t < 64) {
        int k = t >> 1, c = t & 1;
        float s = 0.f;
        for (int o = 0; o < OUTD; o++) s += root2[k * OUTD + o] * lin_w[o * 2 + c];
        g_r2p[t] = s;
    }
    if (t < 2) {
        float s = lin_b[t];
        for (int o = 0; o < OUTD; o++) s += b2[o] * lin_w[o * 2 + t];
        g_bp[t] = s;
    }
}

// -------- zero accumulators (agg1, acc2, deg) --------
__global__ void zero_kernel() {
    int t = blockIdx.x * blockDim.x + threadIdx.x;
    int stride = gridDim.x * blockDim.x;
    float4 z = make_float4(0.f, 0.f, 0.f, 0.f);
    for (int i = t; i < NN * (HID / 4); i += stride) ((float4*)g_agg1)[i] = z;
    for (int i = t; i < NN / 2; i += stride)         ((float4*)g_acc2)[i] = z;
    for (int i = t; i < NN / 4; i += stride)         ((float4*)g_deg)[i]  = z;
}

// -------- tf32 tensor-core GEMM: y1[N,288] = x[N,128] @ wcat[128,288] --------
#define GBM 128
#define GBN 96
#define GBK 32

__device__ __forceinline__ uint32_t f2tf(float f) {
    uint32_t r;
    asm("cvt.rna.tf32.f32 %0, %1;" : "=r"(r) : "f"(f));
    return r;
}

__global__ __launch_bounds__(256) void gemm_tf32_kernel(const float* __restrict__ x) {
    __shared__ uint32_t As[GBM][36];   // padded: bank = (4*row + col) & 31
    __shared__ uint32_t Bs[GBK][100];  // padded: bank = (4*k + n) & 31
    int tid  = threadIdx.x;
    int lane = tid & 31, wid = tid >> 5;
    int warp_m = wid & 3, warp_n = wid >> 2;      // 4x2 warp grid
    int br = blockIdx.x * GBM;
    int bc = blockIdx.y * GBN;
    int gID = lane >> 2, tig = lane & 3;

    float c[2][6][4];
#pragma unroll
    for (int mt = 0; mt < 2; mt++)
#pragma unroll
        for (int nt = 0; nt < 6; nt++)
#pragma unroll
            for (int q = 0; q < 4; q++) c[mt][nt][q] = 0.f;

    int a_row  = tid >> 1;            // 0..127
    int a_half = (tid & 1) * 16;      // 0 or 16
    int b_kk   = tid >> 3;            // 0..31
    int b_seg  = (tid & 7) * 12;      // 0..84

    for (int k0 = 0; k0 < IND; k0 += GBK) {
        // load A tile (128x32) with tf32 conversion
        {
            int gr = br + a_row;
            const float* src = x + (size_t)gr * IND + k0 + a_half;
#pragma unroll
            for (int i = 0; i < 4; i++) {
                float4 v = (gr < NN) ? *(const float4*)(src + i * 4)
                                     : make_float4(0.f, 0.f, 0.f, 0.f);
                As[a_row][a_half + i * 4 + 0] = f2tf(v.x);
                As[a_row][a_half + i * 4 + 1] = f2tf(v.y);
                As[a_row][a_half + i * 4 + 2] = f2tf(v.z);
                As[a_row][a_half + i * 4 + 3] = f2tf(v.w);
            }
        }
        // load B tile (32x96) with tf32 conversion
        {
            const float* src = g_wcat + (k0 + b_kk) * NCOL + bc + b_seg;
#pragma unroll
            for (int i = 0; i < 3; i++) {
                float4 v = *(const float4*)(src + i * 4);
                Bs[b_kk][b_seg + i * 4 + 0] = f2tf(v.x);
                Bs[b_kk][b_seg + i * 4 + 1] = f2tf(v.y);
                Bs[b_kk][b_seg + i * 4 + 2] = f2tf(v.z);
                Bs[b_kk][b_seg + i * 4 + 3] = f2tf(v.w);
            }
        }
        __syncthreads();

#pragma unroll
        for (int ks = 0; ks < 4; ks++) {
            int kb = ks * 8;
            uint32_t a[2][4];
#pragma unroll
            for (int mt = 0; mt < 2; mt++) {
                int r0 = warp_m * 32 + mt * 16 + gID;
                a[mt][0] = As[r0][kb + tig];
                a[mt][1] = As[r0 + 8][kb + tig];
                a[mt][2] = As[r0][kb + tig + 4];
                a[mt][3] = As[r0 + 8][kb + tig + 4];
            }
            uint32_t b[6][2];
#pragma unroll
            for (int nt = 0; nt < 6; nt++) {
                int col = warp_n * 48 + nt * 8 + gID;
                b[nt][0] = Bs[kb + tig][col];
                b[nt][1] = Bs[kb + tig + 4][col];
            }
#pragma unroll
            for (int mt = 0; mt < 2; mt++)
#pragma unroll
                for (int nt = 0; nt < 6; nt++)
                    asm volatile(
                        "mma.sync.aligned.m16n8k8.row.col.f32.tf32.tf32.f32 "
                        "{%0,%1,%2,%3}, {%4,%5,%6,%7}, {%8,%9}, {%0,%1,%2,%3};"
                        : "+f"(c[mt][nt][0]), "+f"(c[mt][nt][1]),
                          "+f"(c[mt][nt][2]), "+f"(c[mt][nt][3])
                        : "r"(a[mt][0]), "r"(a[mt][1]), "r"(a[mt][2]), "r"(a[mt][3]),
                          "r"(b[nt][0]), "r"(b[nt][1]));
        }
        __syncthreads();
    }

    // epilogue: write y1
#pragma unroll
    for (int mt = 0; mt < 2; mt++) {
        int row0 = br + warp_m * 32 + mt * 16 + gID;
#pragma unroll
        for (int nt = 0; nt < 6; nt++) {
            int col = bc + warp_n * 48 + nt * 8 + 2 * tig;
            if (row0 < NN)
                *(float2*)&g_y1[(size_t)row0 * NCOL + col] =
                    make_float2(c[mt][nt][0], c[mt][nt][1]);
            if (row0 + 8 < NN)
                *(float2*)&g_y1[(size_t)(row0 + 8) * NCOL + col] =
                    make_float2(c[mt][nt][2], c[mt][nt][3]);
        }
    }
}

// -------- layer-1 scatter: agg1[dst] += y1[src, rel] (32 floats) + degree --------
__global__ __launch_bounds__(256) void scatter1_kernel(const void* __restrict__ ei,
                                                       const void* __restrict__ et) {
    int t = blockIdx.x * blockDim.x + threadIdx.x;   // NE*8 threads exactly
    int e = t >> 3, c = t & 7;
    int src = edge_at(ei, e);
    int dst = edge_at(ei, (size_t)NE + e);
    int r   = edge_at(et, e);
    float4 v = *(const float4*)&g_y1[(size_t)src * NCOL + r * HID + c * 4];
    atomicAdd((float4*)&g_agg1[dst * HID + c * 4], v);
    if (c == 0) atomicAdd(&g_deg[dst], 1.0f);
}

// -------- h = relu(agg1/deg + x@root1 + b1);  y2[n,r,:] = h[n] @ W2p[r] --------
__global__ __launch_bounds__(256) void h_y2_kernel(const float* __restrict__ b1) {
    __shared__ float sh[32][33];
    __shared__ float sw[512];
    int t = threadIdx.x;
    int n0 = blockIdx.x * 32;
    sw[t] = g_W2p[t];
    sw[t + 256] = g_W2p[t + 256];
#pragma unroll
    for (int j = 0; j < 4; j++) {
        int i = t + j * 256;                 // local elem 0..1023
        int n_l = i >> 5, k = i & 31;
        int n = n0 + n_l;
        int gi = n * 32 + k;
        float d = g_deg[n];
        d = d > 1.f ? d : 1.f;
        float v = g_agg1[gi] / d + g_y1[(size_t)n * NCOL + 256 + k] + b1[k];
        v = v > 0.f ? v : 0.f;
        g_h[gi] = v;
        sh[n_l][k] = v;
    }
    __syncthreads();
    int n_l = t >> 3, r = t & 7;
    float c0 = 0.f, c1 = 0.f;
#pragma unroll
    for (int k = 0; k < 32; k++) {
        float hv = sh[n_l][k];
        float2 w = *(const float2*)&sw[(r * 32 + k) * 2];
        c0 += hv * w.x;
        c1 += hv * w.y;
    }
    *(float2*)&g_y2[(n0 + n_l) * 16 + r * 2] = make_float2(c0, c1);
}

// -------- layer-2 scatter (folded to 2 cols): acc2[dst] += y2[src, r] --------
__global__ __launch_bounds__(256) void scatter2_kernel(const void* __restrict__ ei,
                                                       const void* __restrict__ et) {
    int e = blockIdx.x * blockDim.x + threadIdx.x;   // NE threads exactly
    int src = edge_at(ei, e);
    int dst = edge_at(ei, (size_t)NE + e);
    int r   = edge_at(et, e);
    float2 v = *(const float2*)&g_y2[src * 16 + r * 2];
    atomicAdd((float2*)&g_acc2[dst * 2], v);
}

// -------- out[n] = acc2[n]/deg + h[n] @ r2p + bp --------
__global__ __launch_bounds__(256) void out2_kernel(float* __restrict__ out) {
    int n = blockIdx.x * 256 + threadIdx.x;
    if (n >= NN) return;
    float d = g_deg[n];
    d = d > 1.f ? d : 1.f;
    float inv = 1.f / d;
    float c0 = g_acc2[n * 2 + 0] * inv;
    float c1 = g_acc2[n * 2 + 1] * inv;
#pragma unroll
    for (int k = 0; k < 32; k++) {
        float hv = g_h[n * 32 + k];
        c0 += hv * g_r2p[k * 2 + 0];
        c1 += hv * g_r2p[k * 2 + 1];
    }
    out[n * 2 + 0] = c0 + g_bp[0];
    out[n * 2 + 1] = c1 + g_bp[1];
}

extern "C" void kernel_launch(void* const* d_in, const int* in_sizes, int n_in,
                              void* d_out, int out_size) {
    const float* x     = (const float*)d_in[0];
    const void*  ei    = d_in[1];
    const void*  et    = d_in[2];
    const float* W1    = (const float*)d_in[3];
    const float* root1 = (const float*)d_in[4];
    const float* b1    = (const float*)d_in[5];
    const float* W2    = (const float*)d_in[6];
    const float* root2 = (const float*)d_in[7];
    const float* b2    = (const float*)d_in[8];
    const float* lin_w = (const float*)d_in[9];
    const float* lin_b = (const float*)d_in[10];
    float* out         = (float*)d_out;

    detect_kernel<<<1, 32>>>((const int*)ei);
    prep_kernel<<<145, 256>>>(W1, root1, W2, root2, b2, lin_w, lin_b);
    zero_kernel<<<2048, 256>>>();
    gemm_tf32_kernel<<<dim3((NN + GBM - 1) / GBM, NCOL / GBN), 256>>>(x);
    scatter1_kernel<<<(NE * 8) / 256, 256>>>(ei, et);
    h_y2_kernel<<<NN / 32, 256>>>(b1);
    scatter2_kernel<<<NE / 256, 256>>>(ei, et);
    out2_kernel<<<(NN + 255) / 256, 256>>>(out);
}

// round 6
// speedup vs baseline: 1.7144x; 1.0270x over previous
#include <cuda_runtime.h>
#include <cuda_bf16.h>
#include <cstdint>

#define NN 100000
#define NE 1600000
#define IND 128
#define HID 32
#define OUTD 64
#define NREL 8
#define NCOL 288   // 8*32 + 32 (root)

// -------- scratch (static device memory; 16B-aligned) --------
__device__ __align__(16) float g_wcat[IND * NCOL];      // tf32-rounded packed [k][j]
__device__ __align__(16) float g_xr[(size_t)NN * IND];  // tf32-rounded x (51 MB)
__device__ __align__(16) float g_y1[(size_t)NN * NCOL]; // x @ [W1 | root1]  (115 MB)
__device__ __align__(16) float g_agg1[NN * HID];        // layer-1 aggregation
__device__ __align__(16) float g_deg[NN];
__device__ __align__(16) float g_h[NN * HID];           // layer-1 output (post-relu)
__device__ __align__(16) float g_y2[NN * 16];           // [n][r][c]: h @ W2p  (6.4 MB)
__device__ __align__(16) float g_acc2[NN * 2];          // layer-2 folded accumulator
__device__ __align__(16) float g_W2p[512];              // [(r*32+k)*2+c] = W2 @ lin_w
__device__ __align__(16) float g_r2p[64];               // [k*2+c]        = root2 @ lin_w
__device__ __align__(16) float g_bp[2];                 // b2 @ lin_w + lin_b
__device__ int g_is64;                                  // edge arrays are int64 (vs int32)

__device__ __forceinline__ uint32_t f2tf(float f) {
    uint32_t r;
    asm("cvt.rna.tf32.f32 %0, %1;" : "=r"(r) : "f"(f));
    return r;
}
__device__ __forceinline__ float f2tf_f(float f) { return __uint_as_float(f2tf(f)); }

// -------- dtype detection: int64 layout has zero high words for indices < 2^31 --------
__global__ void detect_kernel(const int* __restrict__ ei_raw) {
    if (threadIdx.x == 0 && blockIdx.x == 0) {
        int is64 = 1;
        for (int i = 0; i < 1024; i++)
            if (ei_raw[2 * i + 1] != 0) { is64 = 0; break; }
        g_is64 = is64;
    }
}

__device__ __forceinline__ int edge_at(const void* __restrict__ p, size_t i) {
    if (g_is64) return (int)((const long long*)p)[i];
    return ((const int*)p)[i];
}

// -------- prep: pack weights (tf32-rounded), fold classifier --------
__global__ void prep_kernel(const float* __restrict__ W1, const float* __restrict__ root1,
                            const float* __restrict__ W2, const float* __restrict__ root2,
                            const float* __restrict__ b2, const float* __restrict__ lin_w,
                            const float* __restrict__ lin_b) {
    int t = blockIdx.x * blockDim.x + threadIdx.x;
    int stride = gridDim.x * blockDim.x;
    for (int i = t; i < IND * NCOL; i += stride) {
        int k = i / NCOL, j = i % NCOL;
        float v;
        if (j < 256) v = W1[(j >> 5) * (IND * HID) + k * HID + (j & 31)];
        else         v = root1[k * HID + (j - 256)];
        g_wcat[i] = f2tf_f(v);
    }
    if (t < 512) {
        int idx = t >> 1, c = t & 1;
        const float* wrow = W2 + idx * OUTD;
        float s = 0.f;
        for (int o = 0; o < OUTD; o++) s += wrow[o] * lin_w[o * 2 + c];
        g_W2p[t] = s;
    }
    if (t < 64) {
        int k = t >> 1, c = t & 1;
        float s = 0.f;
        for (int o = 0; o < OUTD; o++) s += root2[k * OUTD + o] * lin_w[o * 2 + c];
        g_r2p[t] = s;
    }
    if (t < 2) {
        float s = lin_b[t];
        for (int o = 0; o < OUTD; o++) s += b2[o] * lin_w[o * 2 + t];
        g_bp[t] = s;
    }
}

// -------- fused: zero accumulators + pre-round x to tf32 --------
__global__ void roundzero_kernel(const float* __restrict__ x) {
    int t = blockIdx.x * blockDim.x + threadIdx.x;
    int stride = gridDim.x * blockDim.x;
    float4 z = make_float4(0.f, 0.f, 0.f, 0.f);
    for (int i = t; i < NN * (HID / 4); i += stride) ((float4*)g_agg1)[i] = z;
    for (int i = t; i < NN / 2; i += stride)         ((float4*)g_acc2)[i] = z;
    for (int i = t; i < NN / 4; i += stride)         ((float4*)g_deg)[i]  = z;
    for (int i = t; i < NN * (IND / 4); i += stride) {
        float4 v = ((const float4*)x)[i];
        v.x = f2tf_f(v.x); v.y = f2tf_f(v.y); v.z = f2tf_f(v.z); v.w = f2tf_f(v.w);
        ((float4*)g_xr)[i] = v;
    }
}

// -------- tf32 tensor-core GEMM (cp.async double-buffered) --------
#define GBM 128
#define GBN 96
#define GBK 32
#define A_STRIDE 36
#define B_STRIDE 100
#define GEMM_SMEM ((2 * GBM * A_STRIDE + 2 * GBK * B_STRIDE) * 4)

__device__ __forceinline__ void cpa16(uint32_t dst_s, const void* src, int sz) {
    asm volatile("cp.async.ca.shared.global [%0], [%1], 16, %2;\n"
                 :: "r"(dst_s), "l"(src), "r"(sz));
}

__global__ __launch_bounds__(256) void gemm_tf32_kernel() {
    extern __shared__ uint32_t smem[];
    uint32_t* As = smem;                       // [2][GBM][A_STRIDE]
    uint32_t* Bs = smem + 2 * GBM * A_STRIDE;  // [2][GBK][B_STRIDE]
    uint32_t smem_base = (uint32_t)__cvta_generic_to_shared(smem);
    uint32_t bs_base = smem_base + 2 * GBM * A_STRIDE * 4;

    int tid  = threadIdx.x;
    int lane = tid & 31, wid = tid >> 5;
    int warp_m = wid & 3, warp_n = wid >> 2;      // 4x2 warp grid
    int br = blockIdx.x * GBM;
    int bc = blockIdx.y * GBN;
    int gID = lane >> 2, tig = lane & 3;

    float c[2][6][4];
#pragma unroll
    for (int mt = 0; mt < 2; mt++)
#pragma unroll
        for (int nt = 0; nt < 6; nt++)
#pragma unroll
            for (int q = 0; q < 4; q++) c[mt][nt][q] = 0.f;

    // ---- async tile loaders ----
    auto load_stage = [&](int s, int k0) {
        uint32_t a_base = smem_base + (uint32_t)s * GBM * A_STRIDE * 4;
        uint32_t b_base = bs_base + (uint32_t)s * GBK * B_STRIDE * 4;
#pragma unroll
        for (int j = 0; j < 4; j++) {            // A: 128 rows x 8 chunks
            int cch = tid + j * 256;
            int row = cch >> 3, kc = cch & 7;
            int gr = br + row;
            const float* src = g_xr + (size_t)(gr < NN ? gr : 0) * IND + k0 + kc * 4;
            cpa16(a_base + (row * A_STRIDE + kc * 4) * 4, src, gr < NN ? 16 : 0);
        }
#pragma unroll
        for (int j = 0; j < 3; j++) {            // B: 32 rows x 24 chunks
            int cch = tid + j * 256;
            int row = cch / 24, seg = cch % 24;
            const float* src = g_wcat + (k0 + row) * NCOL + bc + seg * 4;
            cpa16(b_base + (row * B_STRIDE + seg * 4) * 4, src, 16);
        }
    };

    load_stage(0, 0);
    asm volatile("cp.async.commit_group;\n");

#pragma unroll
    for (int it = 0; it < 4; it++) {
        if (it < 3) {
            load_stage((it + 1) & 1, (it + 1) * GBK);
            asm volatile("cp.async.commit_group;\n");
            asm volatile("cp.async.wait_group 1;\n");
        } else {
            asm volatile("cp.async.wait_group 0;\n");
        }
        __syncthreads();

        const uint32_t* Ac = As + (it & 1) * GBM * A_STRIDE;
        const uint32_t* Bc = Bs + (it & 1) * GBK * B_STRIDE;
#pragma unroll
        for (int ks = 0; ks < 4; ks++) {
            int kb = ks * 8;
            uint32_t a[2][4];
#pragma unroll
            for (int mt = 0; mt < 2; mt++) {
                int r0 = warp_m * 32 + mt * 16 + gID;
                a[mt][0] = Ac[r0 * A_STRIDE + kb + tig];
                a[mt][1] = Ac[(r0 + 8) * A_STRIDE + kb + tig];
                a[mt][2] = Ac[r0 * A_STRIDE + kb + tig + 4];
                a[mt][3] = Ac[(r0 + 8) * A_STRIDE + kb + tig + 4];
            }
            uint32_t b[6][2];
#pragma unroll
            for (int nt = 0; nt < 6; nt++) {
                int col = warp_n * 48 + nt * 8 + gID;
                b[nt][0] = Bc[(kb + tig) * B_STRIDE + col];
                b[nt][1] = Bc[(kb + tig + 4) * B_STRIDE + col];
            }
#pragma unroll
            for (int mt = 0; mt < 2; mt++)
#pragma unroll
                for (int nt = 0; nt < 6; nt++)
                    asm volatile(
                        "mma.sync.aligned.m16n8k8.row.col.f32.tf32.tf32.f32 "
                        "{%0,%1,%2,%3}, {%4,%5,%6,%7}, {%8,%9}, {%0,%1,%2,%3};"
                        : "+f"(c[mt][nt][0]), "+f"(c[mt][nt][1]),
                          "+f"(c[mt][nt][2]), "+f"(c[mt][nt][3])
                        : "r"(a[mt][0]), "r"(a[mt][1]), "r"(a[mt][2]), "r"(a[mt][3]),
                          "r"(b[nt][0]), "r"(b[nt][1]));
        }
        __syncthreads();
    }

    // epilogue: write y1
#pragma unroll
    for (int mt = 0; mt < 2; mt++) {
        int row0 = br + warp_m * 32 + mt * 16 + gID;
#pragma unroll
        for (int nt = 0; nt < 6; nt++) {
            int col = bc + warp_n * 48 + nt * 8 + 2 * tig;
            if (row0 < NN)
                *(float2*)&g_y1[(size_t)row0 * NCOL + col] =
                    make_float2(c[mt][nt][0], c[mt][nt][1]);
            if (row0 + 8 < NN)
                *(float2*)&g_y1[(size_t)(row0 + 8) * NCOL + col] =
                    make_float2(c[mt][nt][2], c[mt][nt][3]);
        }
    }
}

// -------- layer-1 scatter: agg1[dst] += y1[src, rel] (32 floats) + degree --------
__global__ __launch_bounds__(256) void scatter1_kernel(const void* __restrict__ ei,
                                                       const void* __restrict__ et) {
    int t = blockIdx.x * blockDim.x + threadIdx.x;   // NE*8 threads exactly
    int e = t >> 3, c = t & 7;
    int src = edge_at(ei, e);
    int dst = edge_at(ei, (size_t)NE + e);
    int r   = edge_at(et, e);
    float4 v = *(const float4*)&g_y1[(size_t)src * NCOL + r * HID + c * 4];
    atomicAdd((float4*)&g_agg1[dst * HID + c * 4], v);
    if (c == 0) atomicAdd(&g_deg[dst], 1.0f);
}

// -------- h = relu(agg1/deg + x@root1 + b1);  y2[n,r,:] = h[n] @ W2p[r] --------
__global__ __launch_bounds__(256) void h_y2_kernel(const float* __restrict__ b1) {
    __shared__ float sh[32][33];
    __shared__ float sw[512];
    int t = threadIdx.x;
    int n0 = blockIdx.x * 32;
    sw[t] = g_W2p[t];
    sw[t + 256] = g_W2p[t + 256];
#pragma unroll
    for (int j = 0; j < 4; j++) {
        int i = t + j * 256;
        int n_l = i >> 5, k = i & 31;
        int n = n0 + n_l;
        int gi = n * 32 + k;
        float d = g_deg[n];
        d = d > 1.f ? d : 1.f;
        float v = g_agg1[gi] / d + g_y1[(size_t)n * NCOL + 256 + k] + b1[k];
        v = v > 0.f ? v : 0.f;
        g_h[gi] = v;
        sh[n_l][k] = v;
    }
    __syncthreads();
    int n_l = t >> 3, r = t & 7;
    float c0 = 0.f, c1 = 0.f;
#pragma unroll
    for (int k = 0; k < 32; k++) {
        float hv = sh[n_l][k];
        float2 w = *(const float2*)&sw[(r * 32 + k) * 2];
        c0 += hv * w.x;
        c1 += hv * w.y;
    }
    *(float2*)&g_y2[(n0 + n_l) * 16 + r * 2] = make_float2(c0, c1);
}

// -------- layer-2 scatter (folded to 2 cols): acc2[dst] += y2[src, r] --------
__global__ __launch_bounds__(256) void scatter2_kernel(const void* __restrict__ ei,
                                                       const void* __restrict__ et) {
    int e = blockIdx.x * blockDim.x + threadIdx.x;   // NE threads exactly
    int src = edge_at(ei, e);
    int dst = edge_at(ei, (size_t)NE + e);
    int r   = edge_at(et, e);
    float2 v = *(const float2*)&g_y2[src * 16 + r * 2];
    atomicAdd((float2*)&g_acc2[dst * 2], v);
}

// -------- out[n] = acc2[n]/deg + h[n] @ r2p + bp --------
__global__ __launch_bounds__(256) void out2_kernel(float* __restrict__ out) {
    int n = blockIdx.x * 256 + threadIdx.x;
    if (n >= NN) return;
    float d = g_deg[n];
    d = d > 1.f ? d : 1.f;
    float inv = 1.f / d;
    float c0 = g_acc2[n * 2 + 0] * inv;
    float c1 = g_acc2[n * 2 + 1] * inv;
#pragma unroll
    for (int k = 0; k < 32; k++) {
        float hv = g_h[n * 32 + k];
        c0 += hv * g_r2p[k * 2 + 0];
        c1 += hv * g_r2p[k * 2 + 1];
    }
    out[n * 2 + 0] = c0 + g_bp[0];
    out[n * 2 + 1] = c1 + g_bp[1];
}

extern "C" void kernel_launch(void* const* d_in, const int* in_sizes, int n_in,
                              void* d_out, int out_size) {
    const float* x     = (const float*)d_in[0];
    const void*  ei    = d_in[1];
    const void*  et    = d_in[2];
    const float* W1    = (const float*)d_in[3];
    const float* root1 = (const float*)d_in[4];
    const float* b1    = (const float*)d_in[5];
    const float* W2    = (const float*)d_in[6];
    const float* root2 = (const float*)d_in[7];
    const float* b2    = (const float*)d_in[8];
    const float* lin_w = (const float*)d_in[9];
    const float* lin_b = (const float*)d_in[10];
    float* out         = (float*)d_out;

    cudaFuncSetAttribute(gemm_tf32_kernel,
                         cudaFuncAttributeMaxDynamicSharedMemorySize, GEMM_SMEM);

    detect_kernel<<<1, 32>>>((const int*)ei);
    prep_kernel<<<145, 256>>>(W1, root1, W2, root2, b2, lin_w, lin_b);
    roundzero_kernel<<<4096, 256>>>(x);
    gemm_tf32_kernel<<<dim3((NN + GBM - 1) / GBM, NCOL / GBN), 256, GEMM_SMEM>>>();
    scatter1_kernel<<<(NE * 8) / 256, 256>>>(ei, et);
    h_y2_kernel<<<NN / 32, 256>>>(b1);
    scatter2_kernel<<<NE / 256, 256>>>(ei, et);
    out2_kernel<<<(NN + 255) / 256, 256>>>(out);
}